// round 11
// baseline (speedup 1.0000x reference)
#include <cuda_runtime.h>
#include <cstdint>

typedef unsigned long long u64;
typedef unsigned int u32;

#define NUM_BITS 16
#define THETA 8
#define HN 4096
#define FF 128
#define CC 10
#define BB 64
#define P0 2048                      // F*NUM_BITS
#define SEGS_PER_LAYER (2 * HN)      // 8192
#define HALF_SEGS (SEGS_PER_LAYER / 2)
#define TOT_SEGS (3 * SEGS_PER_LAYER)
#define MAXH 32

#define OUT_BLOCKS 192
#define LH_TOTAL (3 * HN)                      // 12288
#define LH_PER_BLOCK (LH_TOTAL / OUT_BLOCKS)   // 64

// Scratch (device globals: no allocation allowed in kernel_launch)
__device__ u64 g_act[P0];                 // layer-0 input masks
__device__ u64 g_fired[3 * HN];           // per-layer fired masks
__device__ u32 g_cnt[TOT_SEGS];           // hits per segment (<= 32)
__device__ u32 g_hits[TOT_SEGS * MAXH];   // p | signbit<<31
__device__ float g_part[OUT_BLOCKS * BB * CC];

// -------------------------------------------------------------------------
// Encode: x[B,F] -> g_act[p], p = f*16 + t, bit b = (x[b,f] >= (t+1)/17)
// -------------------------------------------------------------------------
__global__ void encode_kernel(const float* __restrict__ x) {
    int p = blockIdx.x * blockDim.x + threadIdx.x;
    if (p >= P0) return;
    int f = p >> 4;
    int t = p & 15;
    float thr = (float)(t + 1) / (float)(NUM_BITS + 1);
    u64 m = 0ull;
#pragma unroll
    for (int b = 0; b < BB; b++) {
        float v = __ldg(&x[b * FF + f]);
        m |= ((u64)(v >= thr)) << b;
    }
    g_act[p] = m;
}

// -------------------------------------------------------------------------
// Extract: one warp per SEGMENT (grid-sliced). Rolling 8-deep pipeline:
// buffer of 8 uint4s; at step i process v[i&7], then immediately refill that
// slot with step i+8 -> the warp keeps ~8 loads in flight continuously.
// Per step, 4 component ballots assign each nonzero an ordered slot
// (deterministic, no atomics); plain STG into the segment's hit list.
// -------------------------------------------------------------------------
template <int P>
__device__ __forceinline__ void extract_step(uint4 w, int step, int lane,
                                             u32 ltmask, u32* hp, int& base) {
    u32 b0 = __ballot_sync(0xffffffffu, w.x != 0u);
    u32 b1 = __ballot_sync(0xffffffffu, w.y != 0u);
    u32 b2 = __ballot_sync(0xffffffffu, w.z != 0u);
    u32 b3 = __ballot_sync(0xffffffffu, w.w != 0u);
    if (b0 | b1 | b2 | b3) {
        int p = (step * 32 + lane) * 4;
        int o0 = base;
        int o1 = o0 + __popc(b0);
        int o2 = o1 + __popc(b1);
        int o3 = o2 + __popc(b2);
        if (w.x) {
            int s = o0 + __popc(b0 & ltmask);
            if (s < MAXH) hp[s] = (u32)p | (w.x & 0x80000000u);
        }
        if (w.y) {
            int s = o1 + __popc(b1 & ltmask);
            if (s < MAXH) hp[s] = (u32)(p + 1) | (w.y & 0x80000000u);
        }
        if (w.z) {
            int s = o2 + __popc(b2 & ltmask);
            if (s < MAXH) hp[s] = (u32)(p + 2) | (w.z & 0x80000000u);
        }
        if (w.w) {
            int s = o3 + __popc(b3 & ltmask);
            if (s < MAXH) hp[s] = (u32)(p + 3) | (w.w & 0x80000000u);
        }
        base = o3 + __popc(b3);
    }
}

template <int P>
__global__ __launch_bounds__(256) void extract_kernel(
    const float* __restrict__ W, int segbase, int segstart) {
    int seg = segstart + ((blockIdx.x * blockDim.x + threadIdx.x) >> 5);
    int lane = threadIdx.x & 31;
    u32 ltmask = (1u << lane) - 1u;

    const uint4* row = (const uint4*)(W + (size_t)seg * (size_t)P);
    u32* hp = &g_hits[(size_t)(segbase + seg) * MAXH];
    int base = 0;

    constexpr int NS = P / 128;       // uint4 steps per lane: 16 or 32
    uint4 v[8];
#pragma unroll
    for (int k = 0; k < 8; k++)
        v[k] = __ldg(&row[k * 32 + lane]);

#pragma unroll
    for (int i = 0; i < NS; i++) {
        uint4 w = v[i & 7];
        if (i + 8 < NS)                       // refill slot before processing
            v[i & 7] = __ldg(&row[(i + 8) * 32 + lane]);
        extract_step<P>(w, i, lane, ltmask, hp, base);
    }

    if (lane == 0)
        g_cnt[segbase + seg] = (u32)(base > MAXH ? MAXH : base);
}

// -------------------------------------------------------------------------
// Fire: one warp per NEURON. Lane k loads hit k of both segments and the
// corresponding act masks (parallel, one latency exposure). Register-only
// shfl loop accumulates exact integer counts for each lane's two owned
// batches; 2 ballots -> fired mask, plain store. Deterministic.
// -------------------------------------------------------------------------
__global__ __launch_bounds__(256) void fire_kernel(
    const u64* __restrict__ act, int segbase, u64* __restrict__ fired) {
    int h = (blockIdx.x * blockDim.x + threadIdx.x) >> 5;
    int lane = threadIdx.x & 31;
    if (h >= HN) return;

    int seg0 = segbase + 2 * h;
    int n0 = (int)g_cnt[seg0];
    int n1 = (int)g_cnt[seg0 + 1];

    u64 m0 = 0ull, m1 = 0ull;
    int s0 = 0, s1 = 0;
    if (lane < n0) {
        u32 e = __ldg(&g_hits[(size_t)seg0 * MAXH + lane]);
        m0 = __ldg(&act[e & 0x7fffffffu]);
        s0 = ((int)e < 0) ? -1 : 1;
    }
    if (lane < n1) {
        u32 e = __ldg(&g_hits[(size_t)(seg0 + 1) * MAXH + lane]);
        m1 = __ldg(&act[e & 0x7fffffffu]);
        s1 = ((int)e < 0) ? -1 : 1;
    }

    int c0 = 0, c1 = 0, d0 = 0, d1 = 0;
#pragma unroll 8
    for (int k = 0; k < 32; k++) {
        u64 M0 = __shfl_sync(0xffffffffu, m0, k);
        int S0 = __shfl_sync(0xffffffffu, s0, k);
        c0 += S0 * (int)((M0 >> lane) & 1ull);
        c1 += S0 * (int)((M0 >> (lane + 32)) & 1ull);
        u64 M1 = __shfl_sync(0xffffffffu, m1, k);
        int S1 = __shfl_sync(0xffffffffu, s1, k);
        d0 += S1 * (int)((M1 >> lane) & 1ull);
        d1 += S1 * (int)((M1 >> (lane + 32)) & 1ull);
    }

    u32 lo = __ballot_sync(0xffffffffu, (c0 >= THETA) || (d0 >= THETA));
    u32 hi = __ballot_sync(0xffffffffu, (c1 >= THETA) || (d1 >= THETA));
    if (lane == 0) fired[h] = ((u64)hi << 32) | (u64)lo;
}

// -------------------------------------------------------------------------
// Output stage 1: partial sums over (l,h) slices.
// -------------------------------------------------------------------------
__global__ __launch_bounds__(640) void out_partial_kernel(
    const float* __restrict__ oW,
    const u64* __restrict__ fired,
    float* __restrict__ part) {
    int t = threadIdx.x;          // 0..639
    int b = t & 63;
    int c = t >> 6;
    int start = blockIdx.x * LH_PER_BLOCK;
    float acc = 0.0f;
#pragma unroll 16
    for (int i = 0; i < LH_PER_BLOCK; i++) {
        int lh = start + i;       // flat l*H + h
        u64 m = __ldg(&fired[lh]);
        float w = __ldg(&oW[lh * CC + c]);
        acc += w * (float)((m >> b) & 1ull);
    }
    part[blockIdx.x * (BB * CC) + t] = acc;
}

// Output stage 2: deterministic fixed-order reduction of partials.
__global__ void out_reduce_kernel(const float* __restrict__ part,
                                  float* __restrict__ out) {
    int t = threadIdx.x;
    if (t >= BB * CC) return;
    float s = 0.0f;
#pragma unroll
    for (int k = 0; k < OUT_BLOCKS; k++) s += part[k * (BB * CC) + t];
    int b = t & 63;
    int c = t >> 6;
    out[b * CC + c] = s;
}

// -------------------------------------------------------------------------
// Launch: symmetric 3-stream schedule captured into the graph.
//   s0: ex0a -> ex1a -> ex2a
//   s1: ex0b -> ex1b -> ex2b
//   s2: encode -> fire0 -> fire1 -> fire2 -> out (gated per layer by events)
// Streams/events are created ONCE (first, pre-capture call) and reused —
// creating them per call leaked pool memory past graph teardown (R10 fail).
// -------------------------------------------------------------------------
extern "C" void kernel_launch(void* const* d_in, const int* in_sizes, int n_in,
                              void* d_out, int out_size) {
    const float* x  = (const float*)d_in[0];
    const float* W0 = (const float*)d_in[1];
    const float* W1 = (const float*)d_in[2];
    const float* W2 = (const float*)d_in[3];
    const float* oW = (const float*)d_in[4];
    float* out = (float*)d_out;

    u64* act = nullptr;
    u64* fired = nullptr;
    float* part = nullptr;
    cudaGetSymbolAddress((void**)&act, g_act);
    cudaGetSymbolAddress((void**)&fired, g_fired);
    cudaGetSymbolAddress((void**)&part, g_part);

    static cudaStream_t s1 = nullptr, s2 = nullptr;
    static cudaEvent_t eFork, eA0, eA1, eA2, eB0, eB1, eB2, eDone;
    if (s1 == nullptr) {
        cudaStreamCreateWithFlags(&s1, cudaStreamNonBlocking);
        cudaStreamCreateWithFlags(&s2, cudaStreamNonBlocking);
        cudaEventCreateWithFlags(&eFork, cudaEventDisableTiming);
        cudaEventCreateWithFlags(&eA0, cudaEventDisableTiming);
        cudaEventCreateWithFlags(&eA1, cudaEventDisableTiming);
        cudaEventCreateWithFlags(&eA2, cudaEventDisableTiming);
        cudaEventCreateWithFlags(&eB0, cudaEventDisableTiming);
        cudaEventCreateWithFlags(&eB1, cudaEventDisableTiming);
        cudaEventCreateWithFlags(&eB2, cudaEventDisableTiming);
        cudaEventCreateWithFlags(&eDone, cudaEventDisableTiming);
    }

    // fork side streams into the capture
    cudaEventRecord(eFork, 0);
    cudaStreamWaitEvent(s1, eFork, 0);
    cudaStreamWaitEvent(s2, eFork, 0);

    // s2: encode early (only gates fire0)
    encode_kernel<<<(P0 + 255) / 256, 256, 0, s2>>>(x);

    // s0/s1: half-grids of each layer's extract, in layer order
    extract_kernel<P0><<<512, 256>>>(W0, 0, 0);
    extract_kernel<P0><<<512, 256, 0, s1>>>(W0, 0, HALF_SEGS);
    cudaEventRecord(eA0, 0);
    cudaEventRecord(eB0, s1);

    extract_kernel<HN><<<512, 256>>>(W1, SEGS_PER_LAYER, 0);
    extract_kernel<HN><<<512, 256, 0, s1>>>(W1, SEGS_PER_LAYER, HALF_SEGS);
    cudaEventRecord(eA1, 0);
    cudaEventRecord(eB1, s1);

    extract_kernel<HN><<<512, 256>>>(W2, 2 * SEGS_PER_LAYER, 0);
    extract_kernel<HN><<<512, 256, 0, s1>>>(W2, 2 * SEGS_PER_LAYER, HALF_SEGS);
    cudaEventRecord(eA2, 0);
    cudaEventRecord(eB2, s1);

    // s2: fire chain + output, gated per layer
    cudaStreamWaitEvent(s2, eA0, 0);
    cudaStreamWaitEvent(s2, eB0, 0);
    fire_kernel<<<512, 256, 0, s2>>>(act, 0, fired);
    cudaStreamWaitEvent(s2, eA1, 0);
    cudaStreamWaitEvent(s2, eB1, 0);
    fire_kernel<<<512, 256, 0, s2>>>(fired, SEGS_PER_LAYER, fired + HN);
    cudaStreamWaitEvent(s2, eA2, 0);
    cudaStreamWaitEvent(s2, eB2, 0);
    fire_kernel<<<512, 256, 0, s2>>>(fired + HN, 2 * SEGS_PER_LAYER,
                                     fired + 2 * HN);
    out_partial_kernel<<<OUT_BLOCKS, BB * CC, 0, s2>>>(oW, fired, part);
    out_reduce_kernel<<<1, BB * CC, 0, s2>>>(part, out);

    // join everything back into the origin stream (single graph sink)
    cudaEventRecord(eDone, s2);
    cudaStreamWaitEvent(0, eDone, 0);
}

// round 12
// speedup vs baseline: 1.0573x; 1.0573x over previous
#include <cuda_runtime.h>
#include <cstdint>

typedef unsigned long long u64;
typedef unsigned int u32;

#define NUM_BITS 16
#define THETA 8
#define HN 4096
#define FF 128
#define CC 10
#define BB 64
#define P0 2048                      // F*NUM_BITS
#define SEGS_PER_LAYER (2 * HN)      // 8192
#define HALF_SEGS (SEGS_PER_LAYER / 2)
#define TOT_SEGS (3 * SEGS_PER_LAYER)
#define MAXH 32

#define OUT_BLOCKS 192
#define LH_TOTAL (3 * HN)                      // 12288
#define LH_PER_BLOCK (LH_TOTAL / OUT_BLOCKS)   // 64

// Scratch (device globals: no allocation allowed in kernel_launch)
__device__ u64 g_act[P0];                 // layer-0 input masks
__device__ u64 g_fired[3 * HN];           // per-layer fired masks
__device__ u32 g_cnt[TOT_SEGS];           // entries per segment (<= 32)
__device__ u64 g_hits[TOT_SEGS * MAXH];   // packed: 4 x 16b (pos|sign|valid)
__device__ float g_part[OUT_BLOCKS * BB * CC];

// -------------------------------------------------------------------------
// Encode: x[B,F] -> g_act[p], p = f*16 + t, bit b = (x[b,f] >= (t+1)/17)
// -------------------------------------------------------------------------
__global__ void encode_kernel(const float* __restrict__ x) {
    int p = blockIdx.x * blockDim.x + threadIdx.x;
    if (p >= P0) return;
    int f = p >> 4;
    int t = p & 15;
    float thr = (float)(t + 1) / (float)(NUM_BITS + 1);
    u64 m = 0ull;
#pragma unroll
    for (int b = 0; b < BB; b++) {
        float v = __ldg(&x[b * FF + f]);
        m |= ((u64)(v >= thr)) << b;
    }
    g_act[p] = m;
}

// -------------------------------------------------------------------------
// Extract: one warp per SEGMENT (grid-sliced). Rolling 8-deep load pipeline.
// ONE ballot per 16B step: hitting lanes (weight nonzero anywhere in their
// uint4) pack all their component hits into a single u64 entry
//   field j (16b) = pos(12b) | signbit<<12 | valid<<13   (component j)
// and store it at base + popc(bal & ltmask). base advances warp-uniformly.
// Deterministic, no atomics. Entries per segment <= nonzeros <= 32.
// -------------------------------------------------------------------------
__device__ __forceinline__ u32 enc_hit(u32 wb, int p) {
    // wb nonzero -> pos | sign<<12 | valid<<13 ; else 0
    return wb ? ((u32)p | ((wb >> 31) << 12) | (1u << 13)) : 0u;
}

template <int P>
__global__ __launch_bounds__(256) void extract_kernel(
    const float* __restrict__ W, int segbase, int segstart) {
    int seg = segstart + ((blockIdx.x * blockDim.x + threadIdx.x) >> 5);
    int lane = threadIdx.x & 31;
    u32 ltmask = (1u << lane) - 1u;

    const uint4* row = (const uint4*)(W + (size_t)seg * (size_t)P);
    u64* hp = &g_hits[(size_t)(segbase + seg) * MAXH];
    int base = 0;

    constexpr int NS = P / 128;       // uint4 steps per lane: 16 or 32
    uint4 v[8];
#pragma unroll
    for (int k = 0; k < 8; k++)
        v[k] = __ldg(&row[k * 32 + lane]);

#pragma unroll
    for (int i = 0; i < NS; i++) {
        uint4 w = v[i & 7];
        if (i + 8 < NS)                       // refill slot behind processing
            v[i & 7] = __ldg(&row[(i + 8) * 32 + lane]);

        u32 any = (w.x | w.y) | (w.z | w.w);
        u32 bal = __ballot_sync(0xffffffffu, any != 0u);
        if (bal) {                            // warp-uniform branch
            if (any) {                        // ~1 lane per step
                int p = (i * 32 + lane) * 4;
                u64 e = (u64)enc_hit(w.x, p)
                      | ((u64)enc_hit(w.y, p + 1) << 16)
                      | ((u64)enc_hit(w.z, p + 2) << 32)
                      | ((u64)enc_hit(w.w, p + 3) << 48);
                int s = base + __popc(bal & ltmask);
                if (s < MAXH) hp[s] = e;
            }
            base += __popc(bal);
        }
    }
    if (lane == 0)
        g_cnt[segbase + seg] = (u32)(base > MAXH ? MAXH : base);
}

// -------------------------------------------------------------------------
// Fire: one warp per NEURON. Lane k loads packed entry k of each segment
// (parallel). Each lane decodes its <=4 sub-hits, gathers act masks
// (L1-hot 16-32KB table) and accumulates +-mask into 7-plane signed
// bit-sliced counters over all 64 batches (two's complement; subset sums
// bounded +-32 -> exact). One 5-round butterfly per segment sums lanes;
// fired iff count>=8: sign clear and any of bits 3..5 set. Deterministic.
// -------------------------------------------------------------------------
__device__ __forceinline__ void acc_entry(u64 e, const u64* __restrict__ act,
                                          u64* c) {
#pragma unroll
    for (int j = 0; j < 4; j++) {
        u32 f = (u32)(e >> (16 * j)) & 0xFFFFu;
        if (f & (1u << 13)) {
            u64 m = __ldg(&act[f & 0xFFFu]);
            u64 neg = (f & (1u << 12)) ? ~0ull : 0ull;
            u64 a = m, carry = 0;
#pragma unroll
            for (int k = 0; k < 7; k++) {
                u64 ck = c[k];
                u64 x = ck ^ a;
                c[k] = x ^ carry;
                carry = (ck & a) | (carry & x);
                a = m & neg;   // planes 1..6: 0 for +1, m for -1
            }
        }
    }
}

__device__ __forceinline__ u64 reduce_fire(u64* c) {
#pragma unroll
    for (int off = 16; off > 0; off >>= 1) {
        u64 t[7];
#pragma unroll
        for (int k = 0; k < 7; k++)
            t[k] = __shfl_xor_sync(0xffffffffu, c[k], off);
        u64 carry = 0;
#pragma unroll
        for (int k = 0; k < 7; k++) {
            u64 ck = c[k], bk = t[k];
            u64 x = ck ^ bk;
            c[k] = x ^ carry;
            carry = (ck & bk) | (carry & x);
        }
    }
    return ~c[6] & (c[3] | c[4] | c[5]);
}

__global__ __launch_bounds__(256) void fire_kernel(
    const u64* __restrict__ act, int segbase, u64* __restrict__ fired) {
    int h = (blockIdx.x * blockDim.x + threadIdx.x) >> 5;
    int lane = threadIdx.x & 31;
    if (h >= HN) return;

    int seg0 = segbase + 2 * h;
    int n0 = (int)g_cnt[seg0];
    int n1 = (int)g_cnt[seg0 + 1];

    u64 e0 = (lane < n0) ? __ldg(&g_hits[(size_t)seg0 * MAXH + lane]) : 0ull;
    u64 e1 = (lane < n1) ? __ldg(&g_hits[(size_t)(seg0 + 1) * MAXH + lane])
                         : 0ull;

    u64 c[7] = {0, 0, 0, 0, 0, 0, 0};
    acc_entry(e0, act, c);
    u64 fm = reduce_fire(c);
#pragma unroll
    for (int k = 0; k < 7; k++) c[k] = 0ull;
    acc_entry(e1, act, c);
    fm |= reduce_fire(c);

    if (lane == 0) fired[h] = fm;
}

// -------------------------------------------------------------------------
// Output stage 1: partial sums over (l,h) slices.
// -------------------------------------------------------------------------
__global__ __launch_bounds__(640) void out_partial_kernel(
    const float* __restrict__ oW,
    const u64* __restrict__ fired,
    float* __restrict__ part) {
    int t = threadIdx.x;          // 0..639
    int b = t & 63;
    int c = t >> 6;
    int start = blockIdx.x * LH_PER_BLOCK;
    float acc = 0.0f;
#pragma unroll 16
    for (int i = 0; i < LH_PER_BLOCK; i++) {
        int lh = start + i;       // flat l*H + h
        u64 m = __ldg(&fired[lh]);
        float w = __ldg(&oW[lh * CC + c]);
        acc += w * (float)((m >> b) & 1ull);
    }
    part[blockIdx.x * (BB * CC) + t] = acc;
}

// Output stage 2: deterministic fixed-order reduction of partials.
__global__ void out_reduce_kernel(const float* __restrict__ part,
                                  float* __restrict__ out) {
    int t = threadIdx.x;
    if (t >= BB * CC) return;
    float s = 0.0f;
#pragma unroll
    for (int k = 0; k < OUT_BLOCKS; k++) s += part[k * (BB * CC) + t];
    int b = t & 63;
    int c = t >> 6;
    out[b * CC + c] = s;
}

// -------------------------------------------------------------------------
// Launch: symmetric 3-stream schedule captured into the graph.
//   s0: ex0a -> ex1a -> ex2a
//   s1: ex0b -> ex1b -> ex2b
//   s2: encode -> fire0 -> fire1 -> fire2 -> out (gated per layer by events)
// Streams/events created ONCE on the first (pre-capture) call and reused —
// per-call creation leaked stream-pool memory past teardown (R10 fail).
// -------------------------------------------------------------------------
extern "C" void kernel_launch(void* const* d_in, const int* in_sizes, int n_in,
                              void* d_out, int out_size) {
    const float* x  = (const float*)d_in[0];
    const float* W0 = (const float*)d_in[1];
    const float* W1 = (const float*)d_in[2];
    const float* W2 = (const float*)d_in[3];
    const float* oW = (const float*)d_in[4];
    float* out = (float*)d_out;

    u64* act = nullptr;
    u64* fired = nullptr;
    float* part = nullptr;
    cudaGetSymbolAddress((void**)&act, g_act);
    cudaGetSymbolAddress((void**)&fired, g_fired);
    cudaGetSymbolAddress((void**)&part, g_part);

    static cudaStream_t s1 = nullptr, s2 = nullptr;
    static cudaEvent_t eFork, eA0, eA1, eA2, eB0, eB1, eB2, eDone;
    if (s1 == nullptr) {
        cudaStreamCreateWithFlags(&s1, cudaStreamNonBlocking);
        cudaStreamCreateWithFlags(&s2, cudaStreamNonBlocking);
        cudaEventCreateWithFlags(&eFork, cudaEventDisableTiming);
        cudaEventCreateWithFlags(&eA0, cudaEventDisableTiming);
        cudaEventCreateWithFlags(&eA1, cudaEventDisableTiming);
        cudaEventCreateWithFlags(&eA2, cudaEventDisableTiming);
        cudaEventCreateWithFlags(&eB0, cudaEventDisableTiming);
        cudaEventCreateWithFlags(&eB1, cudaEventDisableTiming);
        cudaEventCreateWithFlags(&eB2, cudaEventDisableTiming);
        cudaEventCreateWithFlags(&eDone, cudaEventDisableTiming);
    }

    // fork side streams into the capture
    cudaEventRecord(eFork, 0);
    cudaStreamWaitEvent(s1, eFork, 0);
    cudaStreamWaitEvent(s2, eFork, 0);

    // s2: encode early (only gates fire0)
    encode_kernel<<<(P0 + 255) / 256, 256, 0, s2>>>(x);

    // s0/s1: half-grids of each layer's extract, in layer order
    extract_kernel<P0><<<512, 256>>>(W0, 0, 0);
    extract_kernel<P0><<<512, 256, 0, s1>>>(W0, 0, HALF_SEGS);
    cudaEventRecord(eA0, 0);
    cudaEventRecord(eB0, s1);

    extract_kernel<HN><<<512, 256>>>(W1, SEGS_PER_LAYER, 0);
    extract_kernel<HN><<<512, 256, 0, s1>>>(W1, SEGS_PER_LAYER, HALF_SEGS);
    cudaEventRecord(eA1, 0);
    cudaEventRecord(eB1, s1);

    extract_kernel<HN><<<512, 256>>>(W2, 2 * SEGS_PER_LAYER, 0);
    extract_kernel<HN><<<512, 256, 0, s1>>>(W2, 2 * SEGS_PER_LAYER, HALF_SEGS);
    cudaEventRecord(eA2, 0);
    cudaEventRecord(eB2, s1);

    // s2: fire chain + output, gated per layer
    cudaStreamWaitEvent(s2, eA0, 0);
    cudaStreamWaitEvent(s2, eB0, 0);
    fire_kernel<<<512, 256, 0, s2>>>(act, 0, fired);
    cudaStreamWaitEvent(s2, eA1, 0);
    cudaStreamWaitEvent(s2, eB1, 0);
    fire_kernel<<<512, 256, 0, s2>>>(fired, SEGS_PER_LAYER, fired + HN);
    cudaStreamWaitEvent(s2, eA2, 0);
    cudaStreamWaitEvent(s2, eB2, 0);
    fire_kernel<<<512, 256, 0, s2>>>(fired + HN, 2 * SEGS_PER_LAYER,
                                     fired + 2 * HN);
    out_partial_kernel<<<OUT_BLOCKS, BB * CC, 0, s2>>>(oW, fired, part);
    out_reduce_kernel<<<1, BB * CC, 0, s2>>>(part, out);

    // join everything back into the origin stream (single graph sink)
    cudaEventRecord(eDone, s2);
    cudaStreamWaitEvent(0, eDone, 0);
}